// round 4
// baseline (speedup 1.0000x reference)
#include <cuda_runtime.h>
#include <cuda_fp16.h>

#define NN 100000
#define NE 1600000
#define NS 3
#define DIN 128
#define DOUT 64
#define DEPTH 10

__constant__ float c_t[NS] = {0.1f, 0.2f, 0.3f};

// ---------------- device scratch (static: no allocation allowed) ----------------
// planar layouts: fp32 state [s][n][64], fp16 mirror [s][n][32 half2] (128B rows)
__device__ float   g_emb[NS*NN*DOUT];
__device__ float   g_fA [NS*NN*DOUT];
__device__ float   g_fB [NS*NN*DOUT];
__device__ __half2 g_hA [NS*NN*(DOUT/2)];
__device__ __half2 g_hB [NS*NN*(DOUT/2)];
__device__ int     g_cnt[NN];
__device__ int     g_rowptr[NN+1];
__device__ int     g_cursor[NN];
__device__ float   g_deginv[NN];
__device__ int     g_col[NE];
__device__ int     g_bsum[128];
__device__ int     g_sync[4];        // zero-init at load; reset by last exiting block

// ---------------- fused CSR build: zero + hist + scan (one launch) ----------------
// 98 blocks x 1024 threads: grid <= #SMs so all blocks are co-resident; software
// grid barriers use monotonic counters, reset by the last block to exit.
__device__ __forceinline__ void gbar(int k, int nb) {
    __syncthreads();
    __threadfence();
    if (threadIdx.x == 0) {
        atomicAdd(&g_sync[k], 1);
        while (atomicAdd(&g_sync[k], 0) < nb) { }
    }
    __syncthreads();
}

__global__ void __launch_bounds__(1024) k_build(const int* __restrict__ tgt) {
    int t   = threadIdx.x;
    int bid = blockIdx.x;
    int nb  = gridDim.x;
    int gtid = bid*1024 + t;
    int gsz  = nb*1024;

    // phase 0: zero counts
    for (int i = gtid; i < NN; i += gsz) g_cnt[i] = 0;
    gbar(0, nb);

    // phase 1: histogram over edges
    for (int e = gtid; e < NE; e += gsz) atomicAdd(&g_cnt[tgt[e]], 1);
    gbar(1, nb);

    // phase 2: per-block inclusive scan of counts
    __shared__ int sh[1024];
    int i = bid*1024 + t;
    int v = (i < NN) ? g_cnt[i] : 0;
    sh[t] = v;
    __syncthreads();
    for (int off = 1; off < 1024; off <<= 1) {
        int add = (t >= off) ? sh[t-off] : 0;
        __syncthreads();
        sh[t] += add;
        __syncthreads();
    }
    if (t == 1023) g_bsum[bid] = sh[1023];
    gbar(2, nb);

    // phase 3: each block sums its predecessor totals, emits rowptr/cursor/deginv
    __shared__ int s_off;
    if (t == 0) {
        int run = 0;
        for (int b = 0; b < bid; b++) run += g_bsum[b];
        s_off = run;
    }
    __syncthreads();
    if (i < NN) {
        int excl = sh[t] - v + s_off;
        g_rowptr[i] = excl;
        g_cursor[i] = excl;
        g_deginv[i] = 1.0f / (float)max(v, 1);
    }
    if (gtid == 0) g_rowptr[NN] = NE;

    // exit: last block out resets the sync counters for the next graph replay
    __syncthreads();
    __threadfence();
    if (t == 0) {
        int x = atomicAdd(&g_sync[3], 1);
        if (x == nb - 1) {
            g_sync[0] = 0; g_sync[1] = 0; g_sync[2] = 0; g_sync[3] = 0;
            __threadfence();
        }
    }
}

__global__ void k_fill(const int* __restrict__ src, const int* __restrict__ tgt) {
    int e = blockIdx.x*blockDim.x + threadIdx.x;
    if (e < NE) {
        int p = atomicAdd(&g_cursor[tgt[e]], 1);
        g_col[p] = src[e];
    }
}

// ---------------- emb = data @ Ws + bs (planar) + fp16 mirror into g_hA ----------------
__global__ void k_emb(const float* __restrict__ data, const float* __restrict__ Ws,
                      const float* __restrict__ bs) {
    __shared__ float sd[4*DIN];
    int s  = blockIdx.y;
    int n0 = blockIdx.x * 4;
    int tid = threadIdx.x;
    for (int i = tid; i < 4*DIN; i += 256) sd[i] = data[n0*DIN + i];
    __syncthreads();
    int ln = tid >> 6;      // node within block
    int o  = tid & 63;      // output dim
    const float* W  = Ws + s*DIN*DOUT;
    const float* dr = sd + ln*DIN;
    float acc = bs[s*DOUT + o];
    #pragma unroll 8
    for (int k = 0; k < DIN; k++) acc += dr[k] * W[k*DOUT + o];
    size_t node = (size_t)s*NN + (n0 + ln);
    g_emb[node*DOUT + o] = acc;
    ((__half*)g_hA)[node*DOUT + o] = __float2half_rn(acc);
}

// ---------------- one propagation step, per-scale planar (gridDim.y = scale) ----------
// Gathers read the per-scale fp16 mirror (12.8MB active set -> L2 resident).
// fp32 master path (own row, emb, y) streams with evict-first hints.
__global__ void __launch_bounds__(256) k_prop(const float* __restrict__ x,
                                              const __half2* __restrict__ xh,
                                              float* __restrict__ y,
                                              __half2* __restrict__ yh) {
    int s    = blockIdx.y;
    int w    = (blockIdx.x*blockDim.x + threadIdx.x) >> 5;   // node
    int lane = threadIdx.x & 31;
    if (w >= NN) return;
    int beg = g_rowptr[w], end = g_rowptr[w+1];

    const __half2* xb = xh + (size_t)s*NN*(DOUT/2);
    float ax = 0.f, ay = 0.f;

    int j = beg;
    for (; j + 8 <= end; j += 8) {
        int c[8];
        #pragma unroll
        for (int k = 0; k < 8; k++) c[k] = __ldg(&g_col[j+k]);
        float2 v[8];
        #pragma unroll
        for (int k = 0; k < 8; k++) v[k] = __half22float2(xb[(size_t)c[k]*(DOUT/2) + lane]);
        ax += ((v[0].x + v[1].x) + (v[2].x + v[3].x)) + ((v[4].x + v[5].x) + (v[6].x + v[7].x));
        ay += ((v[0].y + v[1].y) + (v[2].y + v[3].y)) + ((v[4].y + v[5].y) + (v[6].y + v[7].y));
    }
    for (; j < end; j++) {
        int c = __ldg(&g_col[j]);
        float2 v = __half22float2(xb[(size_t)c*(DOUT/2) + lane]);
        ax += v.x; ay += v.y;
    }

    size_t roff = ((size_t)s*NN + w)*(DOUT/2);   // float2 / half2 units
    const float2* em = (const float2*)g_emb + roff;
    float2*       yr = (float2*)y + roff;
    __half2*      hr = yh + roff;
    float2 e = __ldcs(em + lane);
    float  t = c_t[s];

    float2 r;
    if (end > beg) {
        float dinv = g_deginv[w];
        float2 o = __ldcs((const float2*)x + roff + lane);
        r.x = (1.f - t)*(o.x - ax*dinv) + t*e.x;
        r.y = (1.f - t)*(o.y - ay*dinv) + t*e.y;
    } else {
        r = make_float2(t*e.x, t*e.y);
    }
    __stcs(yr + lane, r);
    hr[lane] = __float22half2_rn(r);
}

// ---------------- fused attention epilogue, warp per node (planar reads) ------------
__global__ void k_final(const float* __restrict__ xin, const float* __restrict__ data,
                        const float* __restrict__ W_src, const float* __restrict__ b_src,
                        const float* __restrict__ W_tgt, const float* __restrict__ b_tgt,
                        float* __restrict__ out) {
    __shared__ float sd[8][DIN];
    __shared__ float ss[8][DOUT];
    int wid  = threadIdx.x >> 5;
    int lane = threadIdx.x & 31;
    int n = blockIdx.x*8 + wid;
    if (n >= NN) return;

    float4 dv = ((const float4*)(data + (size_t)n*DIN))[lane];
    ((float4*)sd[wid])[lane] = dv;
    __syncwarp();

    float a0 = b_src[lane], a1 = b_src[lane + 32];
    #pragma unroll 8
    for (int k = 0; k < DIN; k++) {
        float d = sd[wid][k];
        a0 += d * W_src[k*DOUT + lane];
        a1 += d * W_src[k*DOUT + lane + 32];
    }
    ss[wid][lane] = a0; ss[wid][lane + 32] = a1;
    __syncwarp();

    float sc[NS][2];
    #pragma unroll
    for (int s = 0; s < NS; s++) {
        const float* xr = xin + ((size_t)s*NN + n)*DOUT;
        sc[s][0] = fmaxf(xr[lane],      0.f);
        sc[s][1] = fmaxf(xr[lane + 32], 0.f);
    }

    float u0 = 0.f, u1 = 0.f;
    #pragma unroll 8
    for (int o = 0; o < DOUT; o++) {
        float sa = ss[wid][o];
        u0 += W_tgt[lane*DOUT + o]        * sa;
        u1 += W_tgt[(lane + 32)*DOUT + o] * sa;
    }

    float cp = b_tgt[lane]*ss[wid][lane] + b_tgt[lane+32]*ss[wid][lane+32];
    for (int m = 16; m; m >>= 1) cp += __shfl_xor_sync(0xffffffffu, cp, m);

    float lg[NS];
    #pragma unroll
    for (int s = 0; s < NS; s++) {
        float p = sc[s][0]*u0 + sc[s][1]*u1;
        for (int m = 16; m; m >>= 1) p += __shfl_xor_sync(0xffffffffu, p, m);
        lg[s] = p + cp;
    }

    float mx = fmaxf(lg[0], fmaxf(lg[1], lg[2]));
    float e0 = expf(lg[0]-mx), e1 = expf(lg[1]-mx), e2 = expf(lg[2]-mx);
    float inv = 1.f / (e0 + e1 + e2);
    float w0 = e0*inv, w1 = e1*inv, w2 = e2*inv;

    out[(size_t)n*DOUT + lane]      = w0*sc[0][0] + w1*sc[1][0] + w2*sc[2][0];
    out[(size_t)n*DOUT + lane + 32] = w0*sc[0][1] + w1*sc[1][1] + w2*sc[2][1];
}

// ---------------- launch ----------------
extern "C" void kernel_launch(void* const* d_in, const int* in_sizes, int n_in,
                              void* d_out, int out_size) {
    const float* data  = (const float*)d_in[0];
    const int*   src   = (const int*)  d_in[1];
    const int*   tgt   = (const int*)  d_in[2];
    const float* Ws    = (const float*)d_in[3];
    const float* bs    = (const float*)d_in[4];
    const float* W_src = (const float*)d_in[5];
    const float* b_src = (const float*)d_in[6];
    const float* W_tgt = (const float*)d_in[7];
    const float* b_tgt = (const float*)d_in[8];
    float* out = (float*)d_out;

    // launch 0: fused CSR build (zero + hist + scan, grid-barrier kernel)
    k_build<<<98, 1024>>>(tgt);
    // launch 1: CSR fill
    k_fill<<<(NE+255)/256, 256>>>(src, tgt);
    // launch 2: embeddings (planar) + fp16 mirror A
    dim3 ge(NN/4, NS);
    k_emb<<<ge, 256>>>(data, Ws, bs);

    float *pA, *pB, *pE;
    __half2 *hA, *hB;
    cudaGetSymbolAddress((void**)&pE, g_emb);
    cudaGetSymbolAddress((void**)&pA, g_fA);
    cudaGetSymbolAddress((void**)&pB, g_fB);
    cudaGetSymbolAddress((void**)&hA, g_hA);
    cudaGetSymbolAddress((void**)&hB, g_hB);

    // launches 3..12: propagation (launch 3 = profiled window)
    dim3 gp((NN + 7)/8, NS);
    const float*   cur  = pE;  const __half2* curh = hA;
    float*         nxt  = pA;  __half2*       nxth = hB;
    for (int d = 0; d < DEPTH; d++) {
        k_prop<<<gp, 256>>>(cur, curh, nxt, nxth);
        cur  = nxt;  curh = nxth;
        nxt  = (cur  == pA) ? pB : pA;
        nxth = (curh == hA) ? hB : hA;
    }

    // launch 13: fused attention epilogue
    k_final<<<NN/8, 256>>>(cur, data, W_src, b_src, W_tgt, b_tgt, out);
}

// round 5
// speedup vs baseline: 1.0974x; 1.0974x over previous
#include <cuda_runtime.h>
#include <cuda_fp16.h>

#define NN 100000
#define NE 1600000
#define NS 3
#define DIN 128
#define DOUT 64
#define DEPTH 10

__constant__ float c_t[NS] = {0.1f, 0.2f, 0.3f};

// ---------------- device scratch (static: no allocation allowed) ----------------
// planar layouts: fp32 state [s][n][64]; fp16 mirror [s][n][8 uint4] (128B rows)
__device__ float g_emb[NS*NN*DOUT];
__device__ float g_fA [NS*NN*DOUT];
__device__ float g_fB [NS*NN*DOUT];
__device__ uint4 g_hA [NS*NN*8];
__device__ uint4 g_hB [NS*NN*8];
__device__ int   g_cnt[NN];
__device__ int   g_rowptr[NN+1];
__device__ int   g_cursor[NN];
__device__ float g_deginv[NN];
__device__ int   g_col[NE];
__device__ int   g_scan[NN];
__device__ int   g_bsum[128];
__device__ int   g_boff[128];
__device__ int   g_done;     // zero at load; reset by last scan block each call

// ---------------- launch 0: histogram (g_cnt zeroed statically / by fillemb) ----------
__global__ void k_hist(const int* __restrict__ tgt) {
    int e = blockIdx.x*blockDim.x + threadIdx.x;
    if (e < NE) atomicAdd(&g_cnt[tgt[e]], 1);
}

// ---------------- launch 1: fused scan (decoupled last-block finish) ------------------
__global__ void k_scan() {
    __shared__ int sh[1024];
    __shared__ bool s_last;
    int t = threadIdx.x;
    int i = blockIdx.x*1024 + t;
    int v = (i < NN) ? g_cnt[i] : 0;
    sh[t] = v;
    __syncthreads();
    for (int off = 1; off < 1024; off <<= 1) {
        int add = (t >= off) ? sh[t-off] : 0;
        __syncthreads();
        sh[t] += add;
        __syncthreads();
    }
    if (i < NN) g_scan[i] = sh[t];
    if (t == 1023) g_bsum[blockIdx.x] = sh[1023];
    __threadfence();
    if (t == 0) {
        int done = atomicAdd(&g_done, 1);
        s_last = (done == (int)gridDim.x - 1);
    }
    __syncthreads();
    if (!s_last) return;
    __threadfence();
    if (t == 0) {
        int run = 0;
        for (int b = 0; b < (int)gridDim.x; b++) { g_boff[b] = run; run += g_bsum[b]; }
        g_done = 0;
        g_rowptr[NN] = NE;
    }
    __syncthreads();
    for (int k = t; k < NN; k += 1024) {
        int cnt  = g_cnt[k];
        int excl = g_scan[k] - cnt + g_boff[k >> 10];
        g_rowptr[k] = excl;
        g_cursor[k] = excl;
        g_deginv[k] = 1.0f / (float)max(cnt, 1);
    }
}

// ---------------- launch 2: CSR fill (+ re-zero g_cnt) and emb GEMM, fused -----------
// blocks [0, 6250): fill; blocks [6250, 81250): emb (25000 per scale).
__global__ void __launch_bounds__(256) k_fillemb(const int* __restrict__ src,
                                                 const int* __restrict__ tgt,
                                                 const float* __restrict__ data,
                                                 const float* __restrict__ Ws,
                                                 const float* __restrict__ bs) {
    int bid = blockIdx.x;
    if (bid < 6250) {
        int e = bid*256 + threadIdx.x;
        if (e < NE) {
            int p = atomicAdd(&g_cursor[tgt[e]], 1);
            g_col[p] = src[e];
        }
        if (e < NN) g_cnt[e] = 0;     // ready for next replay's k_hist
        return;
    }
    __shared__ float sd[4*DIN];
    int b2 = bid - 6250;
    int s  = b2 / 25000;
    int n0 = (b2 % 25000) * 4;
    int tid = threadIdx.x;
    for (int i = tid; i < 4*DIN; i += 256) sd[i] = data[(size_t)n0*DIN + i];
    __syncthreads();
    int ln = tid >> 6;
    int o  = tid & 63;
    const float* W  = Ws + s*DIN*DOUT;
    const float* dr = sd + ln*DIN;
    float acc = bs[s*DOUT + o];
    #pragma unroll 8
    for (int k = 0; k < DIN; k++) acc += dr[k] * W[k*DOUT + o];
    size_t node = (size_t)s*NN + (n0 + ln);
    g_emb[node*DOUT + o] = acc;
    ((__half*)g_hA)[node*DOUT + o] = __float2half_rn(acc);
}

// ---------------- launches 3..12: propagation, per-scale planar ----------------------
// Warp handles one node; lane groups of 8 cover a 128B fp16 row with one LDG.128,
// so 4 neighbors are gathered per warp-wide load. Unrolled x2 (8 neighbors in flight).
__global__ void __launch_bounds__(256) k_prop(const float* __restrict__ x,
                                              const uint4* __restrict__ xh,
                                              float* __restrict__ y,
                                              uint4* __restrict__ yh) {
    int s    = blockIdx.y;
    int w    = (blockIdx.x*blockDim.x + threadIdx.x) >> 5;
    int lane = threadIdx.x & 31;
    if (w >= NN) return;
    int g  = lane >> 3;        // neighbor slot within warp (0..3)
    int l8 = lane & 7;         // 16B chunk within row (cols l8*8 .. l8*8+7)
    int beg = g_rowptr[w], end = g_rowptr[w+1];

    const uint4* xb = xh + (size_t)s*NN*8;
    float a[8];
    #pragma unroll
    for (int k = 0; k < 8; k++) a[k] = 0.f;

    int j = beg;
    for (; j + 8 <= end; j += 8) {
        int c0 = __ldg(&g_col[j + g]);
        int c1 = __ldg(&g_col[j + 4 + g]);
        uint4 v0 = __ldg(&xb[c0*8 + l8]);
        uint4 v1 = __ldg(&xb[c1*8 + l8]);
        float2 f;
        f = __half22float2(*(const __half2*)&v0.x); a[0]+=f.x; a[1]+=f.y;
        f = __half22float2(*(const __half2*)&v0.y); a[2]+=f.x; a[3]+=f.y;
        f = __half22float2(*(const __half2*)&v0.z); a[4]+=f.x; a[5]+=f.y;
        f = __half22float2(*(const __half2*)&v0.w); a[6]+=f.x; a[7]+=f.y;
        f = __half22float2(*(const __half2*)&v1.x); a[0]+=f.x; a[1]+=f.y;
        f = __half22float2(*(const __half2*)&v1.y); a[2]+=f.x; a[3]+=f.y;
        f = __half22float2(*(const __half2*)&v1.z); a[4]+=f.x; a[5]+=f.y;
        f = __half22float2(*(const __half2*)&v1.w); a[6]+=f.x; a[7]+=f.y;
    }
    if (j + 4 <= end) {
        int c0 = __ldg(&g_col[j + g]);
        uint4 v0 = __ldg(&xb[c0*8 + l8]);
        float2 f;
        f = __half22float2(*(const __half2*)&v0.x); a[0]+=f.x; a[1]+=f.y;
        f = __half22float2(*(const __half2*)&v0.y); a[2]+=f.x; a[3]+=f.y;
        f = __half22float2(*(const __half2*)&v0.z); a[4]+=f.x; a[5]+=f.y;
        f = __half22float2(*(const __half2*)&v0.w); a[6]+=f.x; a[7]+=f.y;
        j += 4;
    }
    // remainder (<4): distribute one edge per lane-group
    if (j + g < end) {
        int c = __ldg(&g_col[j + g]);
        uint4 v = __ldg(&xb[c*8 + l8]);
        float2 f;
        f = __half22float2(*(const __half2*)&v.x); a[0]+=f.x; a[1]+=f.y;
        f = __half22float2(*(const __half2*)&v.y); a[2]+=f.x; a[3]+=f.y;
        f = __half22float2(*(const __half2*)&v.z); a[4]+=f.x; a[5]+=f.y;
        f = __half22float2(*(const __half2*)&v.w); a[6]+=f.x; a[7]+=f.y;
    }

    // combine the 4 neighbor-slot partials (all lanes end with full sums)
    #pragma unroll
    for (int k = 0; k < 8; k++) {
        a[k] += __shfl_xor_sync(0xffffffffu, a[k], 8);
        a[k] += __shfl_xor_sync(0xffffffffu, a[k], 16);
    }

    // epilogue: group 0 (8 lanes) writes the full row
    if (g != 0) return;
    size_t roff = ((size_t)s*NN + w)*DOUT;      // in floats
    float t = c_t[s];
    const float4* em = (const float4*)(g_emb + roff);
    float4 e0 = __ldcs(em + 2*l8), e1 = __ldcs(em + 2*l8 + 1);
    float r[8];
    if (end > beg) {
        float dinv = g_deginv[w];
        const float4* xo = (const float4*)(x + roff);
        float4 o0 = __ldcs(xo + 2*l8), o1 = __ldcs(xo + 2*l8 + 1);
        float it = 1.f - t;
        r[0] = it*(o0.x - a[0]*dinv) + t*e0.x;
        r[1] = it*(o0.y - a[1]*dinv) + t*e0.y;
        r[2] = it*(o0.z - a[2]*dinv) + t*e0.z;
        r[3] = it*(o0.w - a[3]*dinv) + t*e0.w;
        r[4] = it*(o1.x - a[4]*dinv) + t*e1.x;
        r[5] = it*(o1.y - a[5]*dinv) + t*e1.y;
        r[6] = it*(o1.z - a[6]*dinv) + t*e1.z;
        r[7] = it*(o1.w - a[7]*dinv) + t*e1.w;
    } else {
        r[0]=t*e0.x; r[1]=t*e0.y; r[2]=t*e0.z; r[3]=t*e0.w;
        r[4]=t*e1.x; r[5]=t*e1.y; r[6]=t*e1.z; r[7]=t*e1.w;
    }
    float4* yo = (float4*)(y + roff);
    __stcs(yo + 2*l8,     make_float4(r[0], r[1], r[2], r[3]));
    __stcs(yo + 2*l8 + 1, make_float4(r[4], r[5], r[6], r[7]));
    __half2 h0 = __float22half2_rn(make_float2(r[0], r[1]));
    __half2 h1 = __float22half2_rn(make_float2(r[2], r[3]));
    __half2 h2 = __float22half2_rn(make_float2(r[4], r[5]));
    __half2 h3 = __float22half2_rn(make_float2(r[6], r[7]));
    uint4 u;
    u.x = *(const unsigned int*)&h0;
    u.y = *(const unsigned int*)&h1;
    u.z = *(const unsigned int*)&h2;
    u.w = *(const unsigned int*)&h3;
    yh[(size_t)s*NN*8 + (size_t)w*8 + l8] = u;
}

// ---------------- launch 13: fused attention epilogue, warp per node ----------------
__global__ void k_final(const float* __restrict__ xin, const float* __restrict__ data,
                        const float* __restrict__ W_src, const float* __restrict__ b_src,
                        const float* __restrict__ W_tgt, const float* __restrict__ b_tgt,
                        float* __restrict__ out) {
    __shared__ float sd[8][DIN];
    __shared__ float ss[8][DOUT];
    int wid  = threadIdx.x >> 5;
    int lane = threadIdx.x & 31;
    int n = blockIdx.x*8 + wid;
    if (n >= NN) return;

    float4 dv = ((const float4*)(data + (size_t)n*DIN))[lane];
    ((float4*)sd[wid])[lane] = dv;
    __syncwarp();

    float a0 = b_src[lane], a1 = b_src[lane + 32];
    #pragma unroll 8
    for (int k = 0; k < DIN; k++) {
        float d = sd[wid][k];
        a0 += d * W_src[k*DOUT + lane];
        a1 += d * W_src[k*DOUT + lane + 32];
    }
    ss[wid][lane] = a0; ss[wid][lane + 32] = a1;
    __syncwarp();

    float sc[NS][2];
    #pragma unroll
    for (int s = 0; s < NS; s++) {
        const float* xr = xin + ((size_t)s*NN + n)*DOUT;
        sc[s][0] = fmaxf(xr[lane],      0.f);
        sc[s][1] = fmaxf(xr[lane + 32], 0.f);
    }

    float u0 = 0.f, u1 = 0.f;
    #pragma unroll 8
    for (int o = 0; o < DOUT; o++) {
        float sa = ss[wid][o];
        u0 += W_tgt[lane*DOUT + o]        * sa;
        u1 += W_tgt[(lane + 32)*DOUT + o] * sa;
    }

    float cp = b_tgt[lane]*ss[wid][lane] + b_tgt[lane+32]*ss[wid][lane+32];
    for (int m = 16; m; m >>= 1) cp += __shfl_xor_sync(0xffffffffu, cp, m);

    float lg[NS];
    #pragma unroll
    for (int s = 0; s < NS; s++) {
        float p = sc[s][0]*u0 + sc[s][1]*u1;
        for (int m = 16; m; m >>= 1) p += __shfl_xor_sync(0xffffffffu, p, m);
        lg[s] = p + cp;
    }

    float mx = fmaxf(lg[0], fmaxf(lg[1], lg[2]));
    float e0 = expf(lg[0]-mx), e1 = expf(lg[1]-mx), e2 = expf(lg[2]-mx);
    float inv = 1.f / (e0 + e1 + e2);
    float w0 = e0*inv, w1 = e1*inv, w2 = e2*inv;

    out[(size_t)n*DOUT + lane]      = w0*sc[0][0] + w1*sc[1][0] + w2*sc[2][0];
    out[(size_t)n*DOUT + lane + 32] = w0*sc[0][1] + w1*sc[1][1] + w2*sc[2][1];
}

// ---------------- launch ----------------
extern "C" void kernel_launch(void* const* d_in, const int* in_sizes, int n_in,
                              void* d_out, int out_size) {
    const float* data  = (const float*)d_in[0];
    const int*   src   = (const int*)  d_in[1];
    const int*   tgt   = (const int*)  d_in[2];
    const float* Ws    = (const float*)d_in[3];
    const float* bs    = (const float*)d_in[4];
    const float* W_src = (const float*)d_in[5];
    const float* b_src = (const float*)d_in[6];
    const float* W_tgt = (const float*)d_in[7];
    const float* b_tgt = (const float*)d_in[8];
    float* out = (float*)d_out;

    k_hist   <<<(NE+255)/256, 256>>>(tgt);              // launch 0
    k_scan   <<<(NN+1023)/1024, 1024>>>();              // launch 1
    k_fillemb<<<6250 + 25000*NS, 256>>>(src, tgt, data, Ws, bs);  // launch 2

    float *pA, *pB, *pE;
    uint4 *hA, *hB;
    cudaGetSymbolAddress((void**)&pE, g_emb);
    cudaGetSymbolAddress((void**)&pA, g_fA);
    cudaGetSymbolAddress((void**)&pB, g_fB);
    cudaGetSymbolAddress((void**)&hA, g_hA);
    cudaGetSymbolAddress((void**)&hB, g_hB);

    dim3 gp((NN + 7)/8, NS);
    const float* cur  = pE;  const uint4* curh = hA;
    float*       nxt  = pA;  uint4*       nxth = hB;
    for (int d = 0; d < DEPTH; d++) {                   // launches 3..12
        k_prop<<<gp, 256>>>(cur, curh, nxt, nxth);
        cur  = nxt;  curh = nxth;
        nxt  = (cur  == pA) ? pB : pA;
        nxth = (curh == hA) ? hB : hA;
    }

    k_final<<<NN/8, 256>>>(cur, data, W_src, b_src, W_tgt, b_tgt, out);  // launch 13
}

// round 6
// speedup vs baseline: 2.0463x; 1.8647x over previous
#include <cuda_runtime.h>
#include <cuda_fp16.h>

#define NN 100000
#define NE 1600000
#define NS 3
#define DIN 128
#define DOUT 64
#define ROW (NS*DOUT)    /* 192 floats per node state row */
#define HROW 96          /* 96 half2 per node row */
#define DEPTH 10

// ---------------- device scratch (static: no allocation allowed) ----------------
__device__ float   g_emb [NN*ROW];
__device__ float   g_fA  [NN*ROW];
__device__ float   g_fB  [NN*ROW];
__device__ __half2 g_hA  [NN*HROW];
__device__ __half2 g_hB  [NN*HROW];
__device__ int     g_cnt[NN];
__device__ int     g_rowptr[NN+1];
__device__ int     g_cursor[NN];
__device__ float   g_deginv[NN];
__device__ int     g_col[NE];
__device__ int     g_scan[NN];
__device__ int     g_bsum[128];
__device__ int     g_boff[128];
__device__ int     g_done;     // zero at load; reset by last scan block each call

// ---------------- launch 0: histogram (g_cnt zeroed by previous fillemb) ----------
__global__ void k_hist(const int* __restrict__ tgt) {
    int e = blockIdx.x*blockDim.x + threadIdx.x;
    if (e < NE) atomicAdd(&g_cnt[tgt[e]], 1);
}

// ---------------- launch 1: fused scan (decoupled last-block finish) --------------
__global__ void k_scan() {
    __shared__ int sh[1024];
    __shared__ bool s_last;
    int t = threadIdx.x;
    int i = blockIdx.x*1024 + t;
    int v = (i < NN) ? g_cnt[i] : 0;
    sh[t] = v;
    __syncthreads();
    for (int off = 1; off < 1024; off <<= 1) {
        int add = (t >= off) ? sh[t-off] : 0;
        __syncthreads();
        sh[t] += add;
        __syncthreads();
    }
    if (i < NN) g_scan[i] = sh[t];
    if (t == 1023) g_bsum[blockIdx.x] = sh[1023];
    __threadfence();
    if (t == 0) {
        int done = atomicAdd(&g_done, 1);
        s_last = (done == (int)gridDim.x - 1);
    }
    __syncthreads();
    if (!s_last) return;
    __threadfence();
    if (t == 0) {
        int run = 0;
        for (int b = 0; b < (int)gridDim.x; b++) { g_boff[b] = run; run += g_bsum[b]; }
        g_done = 0;
        g_rowptr[NN] = NE;
    }
    __syncthreads();
    for (int k = t; k < NN; k += 1024) {
        int cnt  = g_cnt[k];
        int excl = g_scan[k] - cnt + g_boff[k >> 10];
        g_rowptr[k] = excl;
        g_cursor[k] = excl;
        g_deginv[k] = 1.0f / (float)max(cnt, 1);
    }
}

// ---------------- launch 2: CSR fill (+ re-zero g_cnt) and emb GEMM, fused --------
// blocks [0, 6250): fill; blocks [6250, 81250): emb (25000 per scale).
// emb output layout: interleaved [n][s*64+o], plus fp16 mirror into g_hA.
__global__ void __launch_bounds__(256) k_fillemb(const int* __restrict__ src,
                                                 const int* __restrict__ tgt,
                                                 const float* __restrict__ data,
                                                 const float* __restrict__ Ws,
                                                 const float* __restrict__ bs) {
    int bid = blockIdx.x;
    if (bid < 6250) {
        int e = bid*256 + threadIdx.x;
        if (e < NE) {
            int p = atomicAdd(&g_cursor[tgt[e]], 1);
            g_col[p] = src[e];
        }
        if (e < NN) g_cnt[e] = 0;     // ready for next replay's k_hist
        return;
    }
    __shared__ float sd[4*DIN];
    int b2 = bid - 6250;
    int s  = b2 / 25000;
    int n0 = (b2 % 25000) * 4;
    int tid = threadIdx.x;
    for (int i = tid; i < 4*DIN; i += 256) sd[i] = data[(size_t)n0*DIN + i];
    __syncthreads();
    int ln = tid >> 6;
    int o  = tid & 63;
    const float* W  = Ws + s*DIN*DOUT;
    const float* dr = sd + ln*DIN;
    float acc = bs[s*DOUT + o];
    #pragma unroll 8
    for (int k = 0; k < DIN; k++) acc += dr[k] * W[k*DOUT + o];
    size_t idx = (size_t)(n0 + ln)*ROW + s*DOUT + o;
    g_emb[idx] = acc;
    ((__half*)g_hA)[idx] = __float2half_rn(acc);
}

// ---------------- launches 3..12: one propagation step, all 3 scales fused --------
// (R3 interleaved version: empirically 77us/step.) Gathers read the fp16 mirror;
// fp32 master path (own row, emb, y) streams with evict-first hints.
__global__ void __launch_bounds__(256) k_prop(const float* __restrict__ x,
                                              const __half2* __restrict__ xh,
                                              float* __restrict__ y,
                                              __half2* __restrict__ yh) {
    int w    = (blockIdx.x*blockDim.x + threadIdx.x) >> 5;
    int lane = threadIdx.x & 31;
    if (w >= NN) return;
    int beg = g_rowptr[w], end = g_rowptr[w+1];

    float a0x=0.f,a0y=0.f,a1x=0.f,a1y=0.f,a2x=0.f,a2y=0.f;

    int j = beg;
    for (; j + 4 <= end; j += 4) {
        int c0 = __ldg(&g_col[j+0]);
        int c1 = __ldg(&g_col[j+1]);
        int c2 = __ldg(&g_col[j+2]);
        int c3 = __ldg(&g_col[j+3]);
        const __half2* r0 = xh + (size_t)c0*HROW;
        const __half2* r1 = xh + (size_t)c1*HROW;
        const __half2* r2 = xh + (size_t)c2*HROW;
        const __half2* r3 = xh + (size_t)c3*HROW;
        float2 v00 = __half22float2(r0[lane]);
        float2 v10 = __half22float2(r1[lane]);
        float2 v20 = __half22float2(r2[lane]);
        float2 v30 = __half22float2(r3[lane]);
        float2 v01 = __half22float2(r0[32+lane]);
        float2 v11 = __half22float2(r1[32+lane]);
        float2 v21 = __half22float2(r2[32+lane]);
        float2 v31 = __half22float2(r3[32+lane]);
        float2 v02 = __half22float2(r0[64+lane]);
        float2 v12 = __half22float2(r1[64+lane]);
        float2 v22 = __half22float2(r2[64+lane]);
        float2 v32 = __half22float2(r3[64+lane]);
        a0x += (v00.x + v10.x) + (v20.x + v30.x);
        a0y += (v00.y + v10.y) + (v20.y + v30.y);
        a1x += (v01.x + v11.x) + (v21.x + v31.x);
        a1y += (v01.y + v11.y) + (v21.y + v31.y);
        a2x += (v02.x + v12.x) + (v22.x + v32.x);
        a2y += (v02.y + v12.y) + (v22.y + v32.y);
    }
    for (; j < end; j++) {
        int c = __ldg(&g_col[j]);
        const __half2* r = xh + (size_t)c*HROW;
        float2 v0 = __half22float2(r[lane]);
        float2 v1 = __half22float2(r[32+lane]);
        float2 v2 = __half22float2(r[64+lane]);
        a0x += v0.x; a0y += v0.y;
        a1x += v1.x; a1y += v1.y;
        a2x += v2.x; a2y += v2.y;
    }

    const float2* em = (const float2*)(g_emb + (size_t)w*ROW);
    float2* yr = (float2*)(y + (size_t)w*ROW);
    __half2* hr = yh + (size_t)w*HROW;
    float2 e0 = __ldcs(em + lane), e1 = __ldcs(em + 32 + lane), e2 = __ldcs(em + 64 + lane);
    const float t0 = 0.1f, t1 = 0.2f, t2 = 0.3f;

    float2 r;
    if (end > beg) {
        float dinv = g_deginv[w];
        const float2* xo = (const float2*)(x + (size_t)w*ROW);
        float2 o0 = __ldcs(xo + lane), o1 = __ldcs(xo + 32 + lane), o2 = __ldcs(xo + 64 + lane);
        r.x = (1.f-t0)*(o0.x - a0x*dinv) + t0*e0.x;
        r.y = (1.f-t0)*(o0.y - a0y*dinv) + t0*e0.y;
        __stcs(yr + lane, r);            hr[lane]      = __float22half2_rn(r);
        r.x = (1.f-t1)*(o1.x - a1x*dinv) + t1*e1.x;
        r.y = (1.f-t1)*(o1.y - a1y*dinv) + t1*e1.y;
        __stcs(yr + 32 + lane, r);       hr[32 + lane] = __float22half2_rn(r);
        r.x = (1.f-t2)*(o2.x - a2x*dinv) + t2*e2.x;
        r.y = (1.f-t2)*(o2.y - a2y*dinv) + t2*e2.y;
        __stcs(yr + 64 + lane, r);       hr[64 + lane] = __float22half2_rn(r);
    } else {
        r = make_float2(t0*e0.x, t0*e0.y);
        __stcs(yr + lane, r);            hr[lane]      = __float22half2_rn(r);
        r = make_float2(t1*e1.x, t1*e1.y);
        __stcs(yr + 32 + lane, r);       hr[32 + lane] = __float22half2_rn(r);
        r = make_float2(t2*e2.x, t2*e2.y);
        __stcs(yr + 64 + lane, r);       hr[64 + lane] = __float22half2_rn(r);
    }
}

// ---------------- launch 13: fused attention epilogue, warp per node --------------
// W_tgt is staged TRANSPOSED in shared memory: the u-loop previously did
// lane-strided global loads (32 L1 wavefronts per LDG -> ~1.5ms total). Now
// wt[o*64+lane] is consecutive-per-lane: conflict-free, zero replays.
__global__ void __launch_bounds__(256) k_final(
        const float* __restrict__ xin, const float* __restrict__ data,
        const float* __restrict__ W_src, const float* __restrict__ b_src,
        const float* __restrict__ W_tgt, const float* __restrict__ b_tgt,
        float* __restrict__ out) {
    __shared__ float sd[8][DIN];
    __shared__ float ss[8][DOUT];
    __shared__ float wt[DOUT*DOUT];   // wt[o*64+p] = W_tgt[p*64+o]
    int tid  = threadIdx.x;
    int wid  = tid >> 5;
    int lane = tid & 31;
    int n = blockIdx.x*8 + wid;       // grid = NN/8 exactly; no early returns

    // cooperative transpose of W_tgt (coalesced loads, one-time scattered stores)
    for (int i = tid; i < DOUT*DOUT; i += 256) {
        int p = i >> 6, o = i & 63;
        wt[o*DOUT + p] = W_tgt[i];
    }

    float4 dv = ((const float4*)(data + (size_t)n*DIN))[lane];
    ((float4*)sd[wid])[lane] = dv;
    __syncthreads();                  // covers wt + sd

    // s_att[o] = b_src[o] + data[n] . W_src[:,o]   (coalesced, L1-resident W_src)
    float a0 = b_src[lane], a1 = b_src[lane + 32];
    #pragma unroll 8
    for (int k = 0; k < DIN; k++) {
        float d = sd[wid][k];
        a0 += d * W_src[k*DOUT + lane];
        a1 += d * W_src[k*DOUT + lane + 32];
    }
    ss[wid][lane] = a0; ss[wid][lane + 32] = a1;
    __syncwarp();

    // scales = relu(out10), interleaved layout
    const float* xr = xin + (size_t)n*ROW;
    float sc[NS][2];
    #pragma unroll
    for (int s = 0; s < NS; s++) {
        sc[s][0] = fmaxf(xr[s*DOUT + lane],      0.f);
        sc[s][1] = fmaxf(xr[s*DOUT + lane + 32], 0.f);
    }

    // u[p] = W_tgt[p,:] . s_att  via transposed smem (conflict-free)
    float u0 = 0.f, u1 = 0.f;
    #pragma unroll 8
    for (int o = 0; o < DOUT; o++) {
        float sa = ss[wid][o];
        u0 += wt[o*DOUT + lane]      * sa;
        u1 += wt[o*DOUT + lane + 32] * sa;
    }

    float cp = b_tgt[lane]*ss[wid][lane] + b_tgt[lane+32]*ss[wid][lane+32];
    for (int m = 16; m; m >>= 1) cp += __shfl_xor_sync(0xffffffffu, cp, m);

    float lg[NS];
    #pragma unroll
    for (int s = 0; s < NS; s++) {
        float p = sc[s][0]*u0 + sc[s][1]*u1;
        for (int m = 16; m; m >>= 1) p += __shfl_xor_sync(0xffffffffu, p, m);
        lg[s] = p + cp;
    }

    float mx = fmaxf(lg[0], fmaxf(lg[1], lg[2]));
    float e0 = expf(lg[0]-mx), e1 = expf(lg[1]-mx), e2 = expf(lg[2]-mx);
    float inv = 1.f / (e0 + e1 + e2);
    float w0 = e0*inv, w1 = e1*inv, w2 = e2*inv;

    out[(size_t)n*DOUT + lane]      = w0*sc[0][0] + w1*sc[1][0] + w2*sc[2][0];
    out[(size_t)n*DOUT + lane + 32] = w0*sc[0][1] + w1*sc[1][1] + w2*sc[2][1];
}

// ---------------- launch ----------------
extern "C" void kernel_launch(void* const* d_in, const int* in_sizes, int n_in,
                              void* d_out, int out_size) {
    const float* data  = (const float*)d_in[0];
    const int*   src   = (const int*)  d_in[1];
    const int*   tgt   = (const int*)  d_in[2];
    const float* Ws    = (const float*)d_in[3];
    const float* bs    = (const float*)d_in[4];
    const float* W_src = (const float*)d_in[5];
    const float* b_src = (const float*)d_in[6];
    const float* W_tgt = (const float*)d_in[7];
    const float* b_tgt = (const float*)d_in[8];
    float* out = (float*)d_out;

    k_hist   <<<(NE+255)/256, 256>>>(tgt);                         // launch 0
    k_scan   <<<(NN+1023)/1024, 1024>>>();                         // launch 1
    k_fillemb<<<6250 + 25000*NS, 256>>>(src, tgt, data, Ws, bs);   // launch 2

    float *pA, *pB, *pE;
    __half2 *hA, *hB;
    cudaGetSymbolAddress((void**)&pE, g_emb);
    cudaGetSymbolAddress((void**)&pA, g_fA);
    cudaGetSymbolAddress((void**)&pB, g_fB);
    cudaGetSymbolAddress((void**)&hA, g_hA);
    cudaGetSymbolAddress((void**)&hB, g_hB);

    const float*   cur  = pE;  const __half2* curh = hA;
    float*         nxt  = pA;  __half2*       nxth = hB;
    for (int d = 0; d < DEPTH; d++) {                              // launches 3..12
        k_prop<<<NN/8, 256>>>(cur, curh, nxt, nxth);
        cur  = nxt;  curh = nxth;
        nxt  = (cur  == pA) ? pB : pA;
        nxth = (curh == hA) ? hB : hA;
    }

    k_final<<<NN/8, 256>>>(cur, data, W_src, b_src, W_tgt, b_tgt, out);  // launch 13
}

// round 7
// speedup vs baseline: 2.2085x; 1.0792x over previous
#include <cuda_runtime.h>
#include <cuda_fp16.h>

#define NN 100000
#define NE 1600000
#define NS 3
#define DIN 128
#define DOUT 64
#define ROW (NS*DOUT)    /* 192 floats per node state row */
#define HROW 96          /* 96 half2 per node row */
#define DEPTH 10

// ---------------- device scratch (static: no allocation allowed) ----------------
__device__ float   g_emb [NN*ROW];     // fp32 emb (initial state; own-row read step 0)
__device__ float   g_fA  [NN*ROW];
__device__ float   g_fB  [NN*ROW];
__device__ __half2 g_hA  [NN*HROW];    // fp16 state mirrors (gather targets)
__device__ __half2 g_hB  [NN*HROW];
__device__ __half2 g_temb[NN*HROW];    // fp16 t*emb (teleport term, read every step)
__device__ float   g_wt  [DOUT*DOUT];  // W_tgt transposed: g_wt[o*64+p] = W_tgt[p*64+o]
__device__ int     g_cnt[NN];
__device__ int     g_rowptr[NN+1];
__device__ int     g_cursor[NN];
__device__ float   g_deginv[NN];
__device__ int     g_col[NE];
__device__ int     g_scan[NN];
__device__ int     g_bsum[128];
__device__ int     g_boff[128];
__device__ int     g_done;     // zero at load; reset by last scan block each call

// ---------------- launch 0: histogram (g_cnt zeroed by previous fillemb) ----------
__global__ void k_hist(const int* __restrict__ tgt) {
    int e = blockIdx.x*blockDim.x + threadIdx.x;
    if (e < NE) atomicAdd(&g_cnt[tgt[e]], 1);
}

// ---------------- launch 1: fused scan (decoupled last-block finish) --------------
__global__ void k_scan() {
    __shared__ int sh[1024];
    __shared__ bool s_last;
    int t = threadIdx.x;
    int i = blockIdx.x*1024 + t;
    int v = (i < NN) ? g_cnt[i] : 0;
    sh[t] = v;
    __syncthreads();
    for (int off = 1; off < 1024; off <<= 1) {
        int add = (t >= off) ? sh[t-off] : 0;
        __syncthreads();
        sh[t] += add;
        __syncthreads();
    }
    if (i < NN) g_scan[i] = sh[t];
    if (t == 1023) g_bsum[blockIdx.x] = sh[1023];
    __threadfence();
    if (t == 0) {
        int done = atomicAdd(&g_done, 1);
        s_last = (done == (int)gridDim.x - 1);
    }
    __syncthreads();
    if (!s_last) return;
    __threadfence();
    if (t == 0) {
        int run = 0;
        for (int b = 0; b < (int)gridDim.x; b++) { g_boff[b] = run; run += g_bsum[b]; }
        g_done = 0;
        g_rowptr[NN] = NE;
    }
    __syncthreads();
    for (int k = t; k < NN; k += 1024) {
        int cnt  = g_cnt[k];
        int excl = g_scan[k] - cnt + g_boff[k >> 10];
        g_rowptr[k] = excl;
        g_cursor[k] = excl;
        g_deginv[k] = 1.0f / (float)max(cnt, 1);
    }
}

// ---------------- launch 2: CSR fill + emb GEMM + W_tgt transpose, fused ----------
// blocks [0,6250): fill (+re-zero g_cnt); [6250,81250): emb; 81250: transpose W_tgt.
__global__ void __launch_bounds__(256) k_fillemb(const int* __restrict__ src,
                                                 const int* __restrict__ tgt,
                                                 const float* __restrict__ data,
                                                 const float* __restrict__ Ws,
                                                 const float* __restrict__ bs,
                                                 const float* __restrict__ W_tgt) {
    int bid = blockIdx.x;
    if (bid < 6250) {
        int e = bid*256 + threadIdx.x;
        if (e < NE) {
            int p = atomicAdd(&g_cursor[tgt[e]], 1);
            g_col[p] = src[e];
        }
        if (e < NN) g_cnt[e] = 0;     // ready for next replay's k_hist
        return;
    }
    if (bid == 6250 + 75000) {        // W_tgt transpose (tiny, once)
        for (int i = threadIdx.x; i < DOUT*DOUT; i += 256) {
            int p = i >> 6, o = i & 63;
            g_wt[o*DOUT + p] = W_tgt[i];
        }
        return;
    }
    __shared__ float sd[4*DIN];
    int b2 = bid - 6250;
    int s  = b2 / 25000;
    int n0 = (b2 % 25000) * 4;
    int tid = threadIdx.x;
    for (int i = tid; i < 4*DIN; i += 256) sd[i] = data[(size_t)n0*DIN + i];
    __syncthreads();
    int ln = tid >> 6;
    int o  = tid & 63;
    const float* W  = Ws + s*DIN*DOUT;
    const float* dr = sd + ln*DIN;
    float acc = bs[s*DOUT + o];
    #pragma unroll 8
    for (int k = 0; k < DIN; k++) acc += dr[k] * W[k*DOUT + o];
    size_t idx = (size_t)(n0 + ln)*ROW + s*DOUT + o;
    const float tv[NS] = {0.1f, 0.2f, 0.3f};
    g_emb[idx] = acc;
    ((__half*)g_hA)[idx]   = __float2half_rn(acc);
    ((__half*)g_temb)[idx] = __float2half_rn(tv[s]*acc);
}

// ---------------- launches 3..12: one propagation step, all 3 scales fused --------
// Gathers + teleport term read fp16 (L2-resident hot set ~83MB: mirror+temb+col);
// fp32 master path (own row, y) streams with evict-first hints.
__global__ void __launch_bounds__(256) k_prop(const float* __restrict__ x,
                                              const __half2* __restrict__ xh,
                                              float* __restrict__ y,
                                              __half2* __restrict__ yh) {
    int w    = (blockIdx.x*blockDim.x + threadIdx.x) >> 5;
    int lane = threadIdx.x & 31;
    if (w >= NN) return;
    int beg = g_rowptr[w], end = g_rowptr[w+1];

    float a0x=0.f,a0y=0.f,a1x=0.f,a1y=0.f,a2x=0.f,a2y=0.f;

    int j = beg;
    for (; j + 4 <= end; j += 4) {
        int c0 = __ldg(&g_col[j+0]);
        int c1 = __ldg(&g_col[j+1]);
        int c2 = __ldg(&g_col[j+2]);
        int c3 = __ldg(&g_col[j+3]);
        const __half2* r0 = xh + (size_t)c0*HROW;
        const __half2* r1 = xh + (size_t)c1*HROW;
        const __half2* r2 = xh + (size_t)c2*HROW;
        const __half2* r3 = xh + (size_t)c3*HROW;
        float2 v00 = __half22float2(r0[lane]);
        float2 v10 = __half22float2(r1[lane]);
        float2 v20 = __half22float2(r2[lane]);
        float2 v30 = __half22float2(r3[lane]);
        float2 v01 = __half22float2(r0[32+lane]);
        float2 v11 = __half22float2(r1[32+lane]);
        float2 v21 = __half22float2(r2[32+lane]);
        float2 v31 = __half22float2(r3[32+lane]);
        float2 v02 = __half22float2(r0[64+lane]);
        float2 v12 = __half22float2(r1[64+lane]);
        float2 v22 = __half22float2(r2[64+lane]);
        float2 v32 = __half22float2(r3[64+lane]);
        a0x += (v00.x + v10.x) + (v20.x + v30.x);
        a0y += (v00.y + v10.y) + (v20.y + v30.y);
        a1x += (v01.x + v11.x) + (v21.x + v31.x);
        a1y += (v01.y + v11.y) + (v21.y + v31.y);
        a2x += (v02.x + v12.x) + (v22.x + v32.x);
        a2y += (v02.y + v12.y) + (v22.y + v32.y);
    }
    for (; j < end; j++) {
        int c = __ldg(&g_col[j]);
        const __half2* r = xh + (size_t)c*HROW;
        float2 v0 = __half22float2(r[lane]);
        float2 v1 = __half22float2(r[32+lane]);
        float2 v2 = __half22float2(r[64+lane]);
        a0x += v0.x; a0y += v0.y;
        a1x += v1.x; a1y += v1.y;
        a2x += v2.x; a2y += v2.y;
    }

    const __half2* tm = g_temb + (size_t)w*HROW;   // t*emb, fp16, L2-resident
    float2* yr = (float2*)(y + (size_t)w*ROW);
    __half2* hr = yh + (size_t)w*HROW;
    float2 e0 = __half22float2(tm[lane]);
    float2 e1 = __half22float2(tm[32 + lane]);
    float2 e2 = __half22float2(tm[64 + lane]);
    const float i0 = 0.9f, i1 = 0.8f, i2 = 0.7f;   // (1 - t)

    float2 r;
    if (end > beg) {
        float dinv = g_deginv[w];
        const float2* xo = (const float2*)(x + (size_t)w*ROW);
        float2 o0 = __ldcs(xo + lane), o1 = __ldcs(xo + 32 + lane), o2 = __ldcs(xo + 64 + lane);
        r.x = i0*(o0.x - a0x*dinv) + e0.x;
        r.y = i0*(o0.y - a0y*dinv) + e0.y;
        __stcs(yr + lane, r);            hr[lane]      = __float22half2_rn(r);
        r.x = i1*(o1.x - a1x*dinv) + e1.x;
        r.y = i1*(o1.y - a1y*dinv) + e1.y;
        __stcs(yr + 32 + lane, r);       hr[32 + lane] = __float22half2_rn(r);
        r.x = i2*(o2.x - a2x*dinv) + e2.x;
        r.y = i2*(o2.y - a2y*dinv) + e2.y;
        __stcs(yr + 64 + lane, r);       hr[64 + lane] = __float22half2_rn(r);
    } else {
        r = e0;
        __stcs(yr + lane, r);            hr[lane]      = __float22half2_rn(r);
        r = e1;
        __stcs(yr + 32 + lane, r);       hr[32 + lane] = __float22half2_rn(r);
        r = e2;
        __stcs(yr + 64 + lane, r);       hr[64 + lane] = __float22half2_rn(r);
    }
}

// ---------------- launch 13: fused attention epilogue, warp per node --------------
// wt staged to smem from the PRE-TRANSPOSED global (coalesced, conflict-free).
__global__ void __launch_bounds__(256) k_final(
        const float* __restrict__ xin, const float* __restrict__ data,
        const float* __restrict__ W_src, const float* __restrict__ b_src,
        const float* __restrict__ b_tgt, float* __restrict__ out) {
    __shared__ float sd[8][DIN];
    __shared__ float ss[8][DOUT];
    __shared__ float wt[DOUT*DOUT];
    int tid  = threadIdx.x;
    int wid  = tid >> 5;
    int lane = tid & 31;
    int n = blockIdx.x*8 + wid;       // grid = NN/8 exactly

    // coalesced copy of pre-transposed W_tgt (no conflicts, no redundant transpose)
    for (int i = tid; i < DOUT*DOUT; i += 256) wt[i] = g_wt[i];

    float4 dv = ((const float4*)(data + (size_t)n*DIN))[lane];
    ((float4*)sd[wid])[lane] = dv;
    __syncthreads();

    float a0 = b_src[lane], a1 = b_src[lane + 32];
    #pragma unroll 8
    for (int k = 0; k < DIN; k++) {
        float d = sd[wid][k];
        a0 += d * W_src[k*DOUT + lane];
        a1 += d * W_src[k*DOUT + lane + 32];
    }
    ss[wid][lane] = a0; ss[wid][lane + 32] = a1;
    __syncwarp();

    const float* xr = xin + (size_t)n*ROW;
    float sc[NS][2];
    #pragma unroll
    for (int s = 0; s < NS; s++) {
        sc[s][0] = fmaxf(xr[s*DOUT + lane],      0.f);
        sc[s][1] = fmaxf(xr[s*DOUT + lane + 32], 0.f);
    }

    float u0 = 0.f, u1 = 0.f;
    #pragma unroll 8
    for (int o = 0; o < DOUT; o++) {
        float sa = ss[wid][o];
        u0 += wt[o*DOUT + lane]      * sa;
        u1 += wt[o*DOUT + lane + 32] * sa;
    }

    float cp = b_tgt[lane]*ss[wid][lane] + b_tgt[lane+32]*ss[wid][lane+32];
    for (int m = 16; m; m >>= 1) cp += __shfl_xor_sync(0xffffffffu, cp, m);

    float lg[NS];
    #pragma unroll
    for (int s = 0; s < NS; s++) {
        float p = sc[s][0]*u0 + sc[s][1]*u1;
        for (int m = 16; m; m >>= 1) p += __shfl_xor_sync(0xffffffffu, p, m);
        lg[s] = p + cp;
    }

    float mx = fmaxf(lg[0], fmaxf(lg[1], lg[2]));
    float e0 = expf(lg[0]-mx), e1 = expf(lg[1]-mx), e2 = expf(lg[2]-mx);
    float inv = 1.f / (e0 + e1 + e2);
    float w0 = e0*inv, w1 = e1*inv, w2 = e2*inv;

    out[(size_t)n*DOUT + lane]      = w0*sc[0][0] + w1*sc[1][0] + w2*sc[2][0];
    out[(size_t)n*DOUT + lane + 32] = w0*sc[0][1] + w1*sc[1][1] + w2*sc[2][1];
}

// ---------------- launch ----------------
extern "C" void kernel_launch(void* const* d_in, const int* in_sizes, int n_in,
                              void* d_out, int out_size) {
    const float* data  = (const float*)d_in[0];
    const int*   src   = (const int*)  d_in[1];
    const int*   tgt   = (const int*)  d_in[2];
    const float* Ws    = (const float*)d_in[3];
    const float* bs    = (const float*)d_in[4];
    const float* W_src = (const float*)d_in[5];
    const float* b_src = (const float*)d_in[6];
    const float* W_tgt = (const float*)d_in[7];
    const float* b_tgt = (const float*)d_in[8];
    float* out = (float*)d_out;

    k_hist   <<<(NE+255)/256, 256>>>(tgt);                               // launch 0
    k_scan   <<<(NN+1023)/1024, 1024>>>();                               // launch 1
    k_fillemb<<<6250 + 25000*NS + 1, 256>>>(src, tgt, data, Ws, bs, W_tgt); // launch 2

    float *pA, *pB, *pE;
    __half2 *hA, *hB;
    cudaGetSymbolAddress((void**)&pE, g_emb);
    cudaGetSymbolAddress((void**)&pA, g_fA);
    cudaGetSymbolAddress((void**)&pB, g_fB);
    cudaGetSymbolAddress((void**)&hA, g_hA);
    cudaGetSymbolAddress((void**)&hB, g_hB);

    const float*   cur  = pE;  const __half2* curh = hA;
    float*         nxt  = pA;  __half2*       nxth = hB;
    for (int d = 0; d < DEPTH; d++) {                                    // launches 3..12
        k_prop<<<NN/8, 256>>>(cur, curh, nxt, nxth);
        cur  = nxt;  curh = nxth;
        nxt  = (cur  == pA) ? pB : pA;
        nxth = (curh == hA) ? hB : hA;
    }

    k_final<<<NN/8, 256>>>(cur, data, W_src, b_src, b_tgt, out);         // launch 13
}

// round 8
// speedup vs baseline: 2.7797x; 1.2587x over previous
#include <cuda_runtime.h>
#include <cuda_fp16.h>

#define NN 100000
#define NE 1600000
#define NS 3
#define DIN 128
#define DOUT 64
#define ROW (NS*DOUT)    /* 192 halfs per node state row */
#define HROW 96          /* 96 half2 per node row */
#define DEPTH 10

// ---------------- device scratch (static: no allocation allowed) ----------------
__device__ __half2 g_hA  [NN*HROW];    // fp16 state (double buffered)
__device__ __half2 g_hB  [NN*HROW];
__device__ __half2 g_temb[NN*HROW];    // fp16 t*emb (teleport term)
__device__ float   g_wt  [DOUT*DOUT];  // W_tgt transposed: g_wt[o*64+p] = W_tgt[p*64+o]
__device__ int     g_cnt[NN];
__device__ int     g_rowptr[NN+1];
__device__ int     g_cursor[NN];
__device__ float   g_deginv[NN];
__device__ int     g_col[NE];
__device__ int     g_scan[NN];
__device__ int     g_bsum[128];
__device__ int     g_boff[128];
__device__ int     g_done;     // zero at load; reset by last scan block each call

// ---------------- launch 0: histogram (g_cnt zeroed by previous fillemb) ----------
__global__ void k_hist(const int* __restrict__ tgt) {
    int e = blockIdx.x*blockDim.x + threadIdx.x;
    if (e < NE) atomicAdd(&g_cnt[tgt[e]], 1);
}

// ---------------- launch 1: fused scan (decoupled last-block finish) --------------
__global__ void k_scan() {
    __shared__ int sh[1024];
    __shared__ bool s_last;
    int t = threadIdx.x;
    int i = blockIdx.x*1024 + t;
    int v = (i < NN) ? g_cnt[i] : 0;
    sh[t] = v;
    __syncthreads();
    for (int off = 1; off < 1024; off <<= 1) {
        int add = (t >= off) ? sh[t-off] : 0;
        __syncthreads();
        sh[t] += add;
        __syncthreads();
    }
    if (i < NN) g_scan[i] = sh[t];
    if (t == 1023) g_bsum[blockIdx.x] = sh[1023];
    __threadfence();
    if (t == 0) {
        int done = atomicAdd(&g_done, 1);
        s_last = (done == (int)gridDim.x - 1);
    }
    __syncthreads();
    if (!s_last) return;
    __threadfence();
    if (t == 0) {
        int run = 0;
        for (int b = 0; b < (int)gridDim.x; b++) { g_boff[b] = run; run += g_bsum[b]; }
        g_done = 0;
        g_rowptr[NN] = NE;
    }
    __syncthreads();
    for (int k = t; k < NN; k += 1024) {
        int cnt  = g_cnt[k];
        int excl = g_scan[k] - cnt + g_boff[k >> 10];
        g_rowptr[k] = excl;
        g_cursor[k] = excl;
        g_deginv[k] = 1.0f / (float)max(cnt, 1);
    }
}

// ---------------- launch 2: CSR fill + emb GEMM + W_tgt transpose, fused ----------
// blocks [0,6250): fill (+re-zero g_cnt); [6250,25000): emb; 25000: transpose W_tgt.
// emb: block = 16 nodes x 1 scale; thread computes 4 outputs with float4 W loads.
__global__ void __launch_bounds__(256) k_fillemb(const int* __restrict__ src,
                                                 const int* __restrict__ tgt,
                                                 const float* __restrict__ data,
                                                 const float* __restrict__ Ws,
                                                 const float* __restrict__ bs,
                                                 const float* __restrict__ W_tgt) {
    int bid = blockIdx.x;
    int tid = threadIdx.x;
    if (bid < 6250) {
        int e = bid*256 + tid;
        if (e < NE) {
            int p = atomicAdd(&g_cursor[tgt[e]], 1);
            g_col[p] = src[e];
        }
        if (e < NN) g_cnt[e] = 0;     // ready for next replay's k_hist
        return;
    }
    if (bid == 6250 + 18750) {        // W_tgt transpose (tiny, once)
        for (int i = tid; i < DOUT*DOUT; i += 256) {
            int p = i >> 6, o = i & 63;
            g_wt[o*DOUT + p] = W_tgt[i];
        }
        return;
    }
    __shared__ float sd[16][DIN+1];   // +1 pad: rows land in different banks
    int b2 = bid - 6250;              // 0..18749
    int s  = b2 / 6250;               // scale
    int n0 = (b2 % 6250) * 16;        // first node
    for (int i = tid; i < 16*DIN; i += 256) {
        int rrow = i >> 7, col = i & 127;
        sd[rrow][col] = data[(size_t)n0*DIN + i];
    }
    __syncthreads();
    int row = tid >> 4;               // node within block (0..15)
    int og  = tid & 15;               // output group: outs og*4 .. og*4+3
    const float4* W4 = (const float4*)(Ws + (size_t)s*DIN*DOUT);
    float acc0 = bs[s*DOUT + og*4 + 0];
    float acc1 = bs[s*DOUT + og*4 + 1];
    float acc2 = bs[s*DOUT + og*4 + 2];
    float acc3 = bs[s*DOUT + og*4 + 3];
    #pragma unroll 4
    for (int k = 0; k < DIN; k++) {
        float d = sd[row][k];
        float4 wv = W4[k*16 + og];
        acc0 += d*wv.x; acc1 += d*wv.y; acc2 += d*wv.z; acc3 += d*wv.w;
    }
    const float tv[NS] = {0.1f, 0.2f, 0.3f};
    float t = tv[s];
    size_t idx2 = ((size_t)(n0 + row)*ROW + s*DOUT + og*4) >> 1;  // in half2 units
    g_hA[idx2]     = __floats2half2_rn(acc0, acc1);
    g_hA[idx2 + 1] = __floats2half2_rn(acc2, acc3);
    g_temb[idx2]     = __floats2half2_rn(t*acc0, t*acc1);
    g_temb[idx2 + 1] = __floats2half2_rn(t*acc2, t*acc3);
}

// ---------------- launches 3..12: one propagation step, all 3 scales fused --------
// State is fp16-only. Hot set (hA + hB + temb + col ~ 122MB) ~ L2 capacity.
__global__ void __launch_bounds__(256) k_prop(const __half2* __restrict__ xh,
                                              __half2* __restrict__ yh) {
    int w    = (blockIdx.x*blockDim.x + threadIdx.x) >> 5;
    int lane = threadIdx.x & 31;
    if (w >= NN) return;
    int beg = g_rowptr[w], end = g_rowptr[w+1];

    float a0x=0.f,a0y=0.f,a1x=0.f,a1y=0.f,a2x=0.f,a2y=0.f;

    int j = beg;
    for (; j + 4 <= end; j += 4) {
        int c0 = __ldg(&g_col[j+0]);
        int c1 = __ldg(&g_col[j+1]);
        int c2 = __ldg(&g_col[j+2]);
        int c3 = __ldg(&g_col[j+3]);
        const __half2* r0 = xh + (size_t)c0*HROW;
        const __half2* r1 = xh + (size_t)c1*HROW;
        const __half2* r2 = xh + (size_t)c2*HROW;
        const __half2* r3 = xh + (size_t)c3*HROW;
        float2 v00 = __half22float2(r0[lane]);
        float2 v10 = __half22float2(r1[lane]);
        float2 v20 = __half22float2(r2[lane]);
        float2 v30 = __half22float2(r3[lane]);
        float2 v01 = __half22float2(r0[32+lane]);
        float2 v11 = __half22float2(r1[32+lane]);
        float2 v21 = __half22float2(r2[32+lane]);
        float2 v31 = __half22float2(r3[32+lane]);
        float2 v02 = __half22float2(r0[64+lane]);
        float2 v12 = __half22float2(r1[64+lane]);
        float2 v22 = __half22float2(r2[64+lane]);
        float2 v32 = __half22float2(r3[64+lane]);
        a0x += (v00.x + v10.x) + (v20.x + v30.x);
        a0y += (v00.y + v10.y) + (v20.y + v30.y);
        a1x += (v01.x + v11.x) + (v21.x + v31.x);
        a1y += (v01.y + v11.y) + (v21.y + v31.y);
        a2x += (v02.x + v12.x) + (v22.x + v32.x);
        a2y += (v02.y + v12.y) + (v22.y + v32.y);
    }
    for (; j < end; j++) {
        int c = __ldg(&g_col[j]);
        const __half2* r = xh + (size_t)c*HROW;
        float2 v0 = __half22float2(r[lane]);
        float2 v1 = __half22float2(r[32+lane]);
        float2 v2 = __half22float2(r[64+lane]);
        a0x += v0.x; a0y += v0.y;
        a1x += v1.x; a1y += v1.y;
        a2x += v2.x; a2y += v2.y;
    }

    const __half2* tm = g_temb + (size_t)w*HROW;
    __half2* hr = yh + (size_t)w*HROW;

    if (end > beg) {
        const __half2* xo = xh + (size_t)w*HROW;
        float dinv = g_deginv[w];
        const float i0 = 0.9f, i1 = 0.8f, i2 = 0.7f;  // (1 - t)
        float2 e0 = __half22float2(tm[lane]);
        float2 e1 = __half22float2(tm[32 + lane]);
        float2 e2 = __half22float2(tm[64 + lane]);
        float2 o0 = __half22float2(xo[lane]);
        float2 o1 = __half22float2(xo[32 + lane]);
        float2 o2 = __half22float2(xo[64 + lane]);
        float2 r;
        r.x = i0*(o0.x - a0x*dinv) + e0.x;
        r.y = i0*(o0.y - a0y*dinv) + e0.y;  hr[lane]      = __float22half2_rn(r);
        r.x = i1*(o1.x - a1x*dinv) + e1.x;
        r.y = i1*(o1.y - a1y*dinv) + e1.y;  hr[32 + lane] = __float22half2_rn(r);
        r.x = i2*(o2.x - a2x*dinv) + e2.x;
        r.y = i2*(o2.y - a2y*dinv) + e2.y;  hr[64 + lane] = __float22half2_rn(r);
    } else {
        hr[lane]      = tm[lane];
        hr[32 + lane] = tm[32 + lane];
        hr[64 + lane] = tm[64 + lane];
    }
}

// ---------------- launch 13: fused attention epilogue, warp per node --------------
// Each lane owns output pair (2*lane, 2*lane+1): all weight streams are float2.
__global__ void __launch_bounds__(256) k_final(
        const __half2* __restrict__ xin, const float* __restrict__ data,
        const float* __restrict__ W_src, const float* __restrict__ b_src,
        const float* __restrict__ b_tgt, float* __restrict__ out) {
    __shared__ float sd[8][DIN];
    __shared__ float ssf[8][DOUT];
    __shared__ float wt[DOUT*DOUT];
    int tid  = threadIdx.x;
    int wid  = tid >> 5;
    int lane = tid & 31;
    int n = blockIdx.x*8 + wid;       // grid = NN/8 exactly

    for (int i = tid; i < DOUT*DOUT; i += 256) wt[i] = g_wt[i];

    float4 dv = ((const float4*)(data + (size_t)n*DIN))[lane];
    ((float4*)sd[wid])[lane] = dv;
    __syncthreads();

    // s_att pair (o = 2*lane, 2*lane+1)
    const float2* ws2 = (const float2*)W_src;
    float2 bsv = ((const float2*)b_src)[lane];
    float a0 = bsv.x, a1 = bsv.y;
    #pragma unroll 8
    for (int k = 0; k < DIN; k++) {
        float d = sd[wid][k];
        float2 wv = ws2[k*32 + lane];
        a0 += d * wv.x;
        a1 += d * wv.y;
    }
    ssf[wid][2*lane]     = a0;
    ssf[wid][2*lane + 1] = a1;
    __syncwarp();

    // scales = relu(state), pair layout
    const __half2* xr = xin + (size_t)n*HROW;
    float sc[NS][2];
    #pragma unroll
    for (int s = 0; s < NS; s++) {
        float2 v = __half22float2(xr[s*32 + lane]);
        sc[s][0] = fmaxf(v.x, 0.f);
        sc[s][1] = fmaxf(v.y, 0.f);
    }

    // u[p] for p = 2*lane, 2*lane+1 via transposed W_tgt (float2)
    const float2* wt2 = (const float2*)wt;
    float u0 = 0.f, u1 = 0.f;
    #pragma unroll 8
    for (int o = 0; o < DOUT; o++) {
        float sa = ssf[wid][o];
        float2 wv = wt2[o*32 + lane];
        u0 += wv.x * sa;
        u1 += wv.y * sa;
    }

    float2 btv = ((const float2*)b_tgt)[lane];
    float cp = btv.x*a0 + btv.y*a1;
    for (int m = 16; m; m >>= 1) cp += __shfl_xor_sync(0xffffffffu, cp, m);

    float lg[NS];
    #pragma unroll
    for (int s = 0; s < NS; s++) {
        float p = sc[s][0]*u0 + sc[s][1]*u1;
        for (int m = 16; m; m >>= 1) p += __shfl_xor_sync(0xffffffffu, p, m);
        lg[s] = p + cp;
    }

    float mx = fmaxf(lg[0], fmaxf(lg[1], lg[2]));
    float e0 = expf(lg[0]-mx), e1 = expf(lg[1]-mx), e2 = expf(lg[2]-mx);
    float inv = 1.f / (e0 + e1 + e2);
    float w0 = e0*inv, w1 = e1*inv, w2 = e2*inv;

    float2 ov;
    ov.x = w0*sc[0][0] + w1*sc[1][0] + w2*sc[2][0];
    ov.y = w0*sc[0][1] + w1*sc[1][1] + w2*sc[2][1];
    ((float2*)out)[(size_t)n*32 + lane] = ov;
}

// ---------------- launch ----------------
extern "C" void kernel_launch(void* const* d_in, const int* in_sizes, int n_in,
                              void* d_out, int out_size) {
    const float* data  = (const float*)d_in[0];
    const int*   src   = (const int*)  d_in[1];
    const int*   tgt   = (const int*)  d_in[2];
    const float* Ws    = (const float*)d_in[3];
    const float* bs    = (const float*)d_in[4];
    const float* W_src = (const float*)d_in[5];
    const float* b_src = (const float*)d_in[6];
    const float* W_tgt = (const float*)d_in[7];
    const float* b_tgt = (const float*)d_in[8];
    float* out = (float*)d_out;

    k_hist   <<<(NE+255)/256, 256>>>(tgt);                                // launch 0
    k_scan   <<<(NN+1023)/1024, 1024>>>();                                // launch 1
    k_fillemb<<<6250 + 18750 + 1, 256>>>(src, tgt, data, Ws, bs, W_tgt);  // launch 2

    __half2 *hA, *hB;
    cudaGetSymbolAddress((void**)&hA, g_hA);
    cudaGetSymbolAddress((void**)&hB, g_hB);

    const __half2* cur = hA;
    __half2*       nxt = hB;
    for (int d = 0; d < DEPTH; d++) {                                     // launches 3..12
        k_prop<<<NN/8, 256>>>(cur, nxt);
        const __half2* tmp = nxt;
        nxt = (__half2*)cur;
        cur = tmp;
    }

    k_final<<<NN/8, 256>>>(cur, data, W_src, b_src, b_tgt, out);          // launch 13
}